// round 8
// baseline (speedup 1.0000x reference)
#include <cuda_runtime.h>
#include <stdint.h>

#define N_TOKENS 131072
#define D_MODEL  512
#define PATHS    16
#define CAP      16384                 // 2 * N / P
#define D4       (D_MODEL / 4)         // 128 float4 per row
#define ROWS     (PATHS * CAP)         // 262144 output rows

#define TPB      512                   // 16 warps
#define NWARP    16
#define NB_R     256                   // route blocks (bid < NB_R): 256*512 = N_TOKENS
#define GROWS_PB 16                    // output rows per block (one per warp)
#define GRID_G   (ROWS / GROWS_PB)     // 16384 blocks

// ---- scratch (no allocations allowed; zero-initialized at load) ----
__device__ int      g_cnt[PATHS];          // per-path count, clamped to CAP
__device__ int      g_slot[ROWS];          // slot -> token gather map
__device__ int      g_hist[PATHS * NB_R];  // per-(path, block) counts  [path][block]
__device__ unsigned g_arrive;              // route-internal barrier counter
__device__ unsigned g_done;                // route completion counter
__device__ unsigned g_flag;                // route->gather release flag
__device__ unsigned g_exit;                // kernel exit counter (self-clean)

__device__ __forceinline__ unsigned vload(const unsigned* p) {
    return *(volatile const unsigned*)p;
}

__global__ __launch_bounds__(TPB, 4) void k_fused(const float* __restrict__ score,
                                                  const float4* __restrict__ in4,
                                                  float4* __restrict__ out4) {
    __shared__ int sh_cnt[NWARP][PATHS];
    __shared__ int sh_wexcl[NWARP][PATHS];
    __shared__ int sh_excl[PATHS];
    __shared__ int sh_run[NWARP][PATHS];
    __shared__ int sh_last;
    const int tid = threadIdx.x, w = tid >> 5, lane = tid & 31, bid = blockIdx.x;

    // ================= ROUTE PHASE (blocks 0..NB_R-1 only) =================
    if (bid < NB_R) {
        const int tok = bid * TPB + tid;               // one token per thread

        // argmax + per-warp per-path counts
        if (lane < PATHS) sh_cnt[w][lane] = 0;
        __syncwarp();
        int best;
        {
            const float4* sc = (const float4*)(score + (size_t)tok * PATHS);
            float4 a = __ldcs(sc), b = __ldcs(sc + 1), c = __ldcs(sc + 2), d = __ldcs(sc + 3);
            float v[16] = {a.x,a.y,a.z,a.w, b.x,b.y,b.z,b.w,
                           c.x,c.y,c.z,c.w, d.x,d.y,d.z,d.w};
            best = 0; float bv = v[0];
            #pragma unroll
            for (int p = 1; p < 16; p++) if (v[p] > bv) { bv = v[p]; best = p; }  // first-max
            unsigned m = __match_any_sync(0xffffffffu, best);
            if ((__ffs(m) - 1) == lane) sh_cnt[w][best] += __popc(m);
        }
        __syncthreads();

        // block scan over 16 warps + publish block aggregate (writers fence)
        if (w == 0 && lane < PATHS) {
            int run = 0;
            #pragma unroll
            for (int ww = 0; ww < NWARP; ww++) { int v = sh_cnt[ww][lane]; sh_wexcl[ww][lane] = run; run += v; }
            g_hist[lane * NB_R + bid] = run;           // [path][block]
            __threadfence();
        }
        __syncthreads();

        // resident-grid barrier over the NB_R route blocks
        if (tid == 0) {
            atomicAdd(&g_arrive, 1u);
            while (vload(&g_arrive) < (unsigned)NB_R) { }
        }
        __syncthreads();

        // bulk prefix: warp w owns path w; read full hist row
        {
            int excl = 0, tot = 0;
            #pragma unroll
            for (int s = 0; s < NB_R / 32; s++) {
                const int j = s * 32 + lane;
                const int v = g_hist[w * NB_R + j];
                tot += v;
                if (j < bid) excl += v;
            }
            excl = __reduce_add_sync(0xffffffffu, excl);
            tot  = __reduce_add_sync(0xffffffffu, tot);
            if (lane == 0) {
                sh_excl[w] = excl;
                if (bid == 0) g_cnt[w] = tot < CAP ? tot : CAP;
            }
        }
        __syncthreads();

        // order-preserving rank -> slot map
        if (lane < PATHS) sh_run[w][lane] = sh_excl[lane] + sh_wexcl[w][lane];
        __syncwarp();
        {
            unsigned m = __match_any_sync(0xffffffffu, best);
            const int rank = __popc(m & ((1u << lane) - 1u));
            const int pos = sh_run[w][best] + rank;
            if (pos < CAP) g_slot[best * CAP + pos] = tok;
        }

        // release: every writing thread fences, then last block raises flag
        __threadfence();
        __syncthreads();
        if (tid == 0) {
            if (atomicAdd(&g_done, 1u) == (unsigned)(NB_R - 1))
                atomicExch(&g_flag, 1u);
        }
    }

    // ================= RELEASE GATE (all blocks) =================
    if (tid == 0) { while (vload(&g_flag) == 0u) { } }
    __syncthreads();

    // ================= GATHER PHASE (identical shape to best kernel) =================
    {
        const int r = bid * GROWS_PB + w;              // output row in [0, ROWS)
        const int p = r >> 14;                         // r / CAP
        const int j = r & (CAP - 1);                   // r % CAP
        float4 v0 = make_float4(0.f,0.f,0.f,0.f);
        float4 v1 = v0, v2 = v0, v3 = v0;
        if (j < g_cnt[p]) {
            const float4* src = in4 + (size_t)g_slot[r] * D4 + lane;
            v0 = src[0];
            v1 = src[32];
            v2 = src[64];
            v3 = src[96];
        }
        float4* dst = out4 + (size_t)r * D4 + lane;
        dst[0]  = v0;
        dst[32] = v1;
        dst[64] = v2;
        dst[96] = v3;
    }

    // ================= SELF-CLEAN (deterministic graph replay) =================
    __syncthreads();
    if (tid == 0) sh_last = (atomicAdd(&g_exit, 1u) == (unsigned)(GRID_G - 1));
    __syncthreads();
    if (sh_last && tid == 0) { g_arrive = 0; g_done = 0; g_flag = 0; g_exit = 0; }
}

extern "C" void kernel_launch(void* const* d_in, const int* in_sizes, int n_in,
                              void* d_out, int out_size) {
    const float* inputs = (const float*)d_in[0];
    const float* score  = (const float*)d_in[1];
    if (in_sizes[0] == N_TOKENS * PATHS) {   // defensive: identify by element count
        inputs = (const float*)d_in[1];
        score  = (const float*)d_in[0];
    }
    k_fused<<<GRID_G, TPB>>>(score, (const float4*)inputs, (float4*)d_out);
}